// round 2
// baseline (speedup 1.0000x reference)
#include <cuda_runtime.h>
#include <math.h>

#define NN 100000
#define EE 1200000
#define AA 256
#define HH 64
#define TT 4
#define BB 64
#define NSTEPS 6

// ---------------- scratch (device globals) -----------------------------------
__device__ float g_h[NN * HH];
__device__ float g_h0[NN * HH];
__device__ float g_a[NN * HH];
__device__ float g_rz[(size_t)NN * 128];
__device__ float g_in[NN * HH];
__device__ float g_hn[NN * HH];
__device__ int   g_rowstart[NN + 1];
__device__ int   g_cursor[NN];
__device__ int   g_eidx[EE];
__device__ int   g_cnt4[NN * 4];
__device__ float g_Wrz[128 * 128];
__device__ float g_Win[64 * 64];
__device__ float g_Whn[64 * 64];
__device__ float g_brz[128];
__device__ float g_bin[64];
__device__ float g_bhn[64];
__device__ float g_gate[NN];
__device__ float g_gmax[BB];
__device__ float g_den[BB];
__device__ float g_rsum[BB * 128];

// ---------------- CSR build ----------------------------------------------------
__global__ void zero_cnt()
{
    int i = blockIdx.x * blockDim.x + threadIdx.x;
    if (i < NN * 4) g_cnt4[i] = 0;
}

__global__ void hist_kernel(const int* __restrict__ dst, const int* __restrict__ ety)
{
    int e = blockIdx.x * blockDim.x + threadIdx.x;
    if (e < EE) atomicAdd(&g_cnt4[dst[e] * 4 + ety[e]], 1);
}

__global__ void scan_kernel()
{
    __shared__ int part[1024];
    int tid = threadIdx.x;
    const int CH = (NN + 1023) / 1024;  // 98
    int base = tid * CH;
    int s = 0;
    for (int i = 0; i < CH; ++i) {
        int n = base + i;
        if (n < NN) s += g_cnt4[n * 4] + g_cnt4[n * 4 + 1] + g_cnt4[n * 4 + 2] + g_cnt4[n * 4 + 3];
    }
    part[tid] = s;
    __syncthreads();
    for (int off = 1; off < 1024; off <<= 1) {
        int v = (tid >= off) ? part[tid - off] : 0;
        __syncthreads();
        part[tid] += v;
        __syncthreads();
    }
    int run = (tid ? part[tid - 1] : 0);
    for (int i = 0; i < CH; ++i) {
        int n = base + i;
        if (n < NN) {
            g_rowstart[n] = run;
            g_cursor[n] = run;
            run += g_cnt4[n * 4] + g_cnt4[n * 4 + 1] + g_cnt4[n * 4 + 2] + g_cnt4[n * 4 + 3];
        }
    }
    if (tid == 1023) g_rowstart[NN] = part[1023];
}

__global__ void fill_kernel(const int* __restrict__ src, const int* __restrict__ dst,
                            const int* __restrict__ ety)
{
    int e = blockIdx.x * blockDim.x + threadIdx.x;
    if (e < EE) {
        int pos = atomicAdd(&g_cursor[dst[e]], 1);
        g_eidx[pos] = (src[e] << 2) | ety[e];
    }
}

// ---------------- weight packing ------------------------------------------------
__global__ void pack2(const float* __restrict__ Wi, const float* __restrict__ Wh,
                      const float* __restrict__ bi, const float* __restrict__ bh)
{
    int i = blockIdx.x * blockDim.x + threadIdx.x;
    if (i < 16384) {                                  // Wrz [128k][128c]
        int k = i >> 7, c = i & 127;
        g_Wrz[i] = (k < 64) ? Wi[c * 64 + k] : Wh[c * 64 + (k - 64)];
    } else if (i < 16384 + 4096) {                    // Win [64k][64c]
        int j = i - 16384; int k = j >> 6, c = j & 63;
        g_Win[j] = Wi[(128 + c) * 64 + k];
    } else if (i < 16384 + 8192) {                    // Whn
        int j = i - 16384 - 4096; int k = j >> 6, c = j & 63;
        g_Whn[j] = Wh[(128 + c) * 64 + k];
    } else if (i < 24576 + 128) {
        int c = i - 24576; g_brz[c] = bi[c] + bh[c];
    } else if (i < 24704 + 64) {
        int c = i - 24704; g_bin[c] = bi[128 + c];
    } else if (i < 24768 + 64) {
        int c = i - 24768; g_bhn[c] = bh[128 + c];
    }
}

// ---------------- generic padded GEMM (64 rows x 64 cols per block) -------------
// C[n][c0+c] = sum_k A[n][k]*W[k][c0+c] + bias.  kch chunks of 64 along K.
// If A2 != nullptr: chunk0 from A1, chunk1 from A2 (both lda=64 logical).
#define SP 68
__global__ __launch_bounds__(256) void gemm_t(
    const float* __restrict__ A1, const float* __restrict__ A2,
    int lda, int kch, const float* __restrict__ W, int ldw,
    const float* __restrict__ bias,
    float* __restrict__ C, float* __restrict__ C2, int ldc, int nrows)
{
    extern __shared__ float sm[];
    float* sA = sm;              // [64][SP]
    float* sW = sm + 64 * SP;    // [64][SP]
    const int tid = threadIdx.x;
    const int tx = tid & 15, ty = tid >> 4;
    const int n0 = blockIdx.x * 64, c0 = blockIdx.y * 64;

    float acc[4][4] = {};
    for (int kc = 0; kc < kch; ++kc) {
        const float* Ap = (A2 && kc > 0) ? A2 : A1;
        const int koff = A2 ? 0 : kc * 64;
        const int kg0 = kc * 64;
#pragma unroll
        for (int i = 0; i < 4; ++i) {
            int idx = tid + i * 256;
            int r = idx >> 4, kq = (idx & 15) << 2;
            int n = n0 + r;
            float4 v = make_float4(0.f, 0.f, 0.f, 0.f);
            if (n < nrows) v = *(const float4*)&Ap[(size_t)n * lda + koff + kq];
            *(float4*)&sA[r * SP + kq] = v;
        }
#pragma unroll
        for (int i = 0; i < 4; ++i) {
            int idx = tid + i * 256;
            int k = idx >> 4, cq = (idx & 15) << 2;
            *(float4*)&sW[k * SP + cq] = *(const float4*)&W[(size_t)(kg0 + k) * ldw + c0 + cq];
        }
        __syncthreads();
#pragma unroll
        for (int kk = 0; kk < 64; ++kk) {
            float4 wv = *(const float4*)&sW[kk * SP + (tx << 2)];
            float a0 = sA[(ty * 4 + 0) * SP + kk];
            float a1 = sA[(ty * 4 + 1) * SP + kk];
            float a2 = sA[(ty * 4 + 2) * SP + kk];
            float a3 = sA[(ty * 4 + 3) * SP + kk];
            acc[0][0] += a0 * wv.x; acc[0][1] += a0 * wv.y; acc[0][2] += a0 * wv.z; acc[0][3] += a0 * wv.w;
            acc[1][0] += a1 * wv.x; acc[1][1] += a1 * wv.y; acc[1][2] += a1 * wv.z; acc[1][3] += a1 * wv.w;
            acc[2][0] += a2 * wv.x; acc[2][1] += a2 * wv.y; acc[2][2] += a2 * wv.z; acc[2][3] += a2 * wv.w;
            acc[3][0] += a3 * wv.x; acc[3][1] += a3 * wv.y; acc[3][2] += a3 * wv.z; acc[3][3] += a3 * wv.w;
        }
        __syncthreads();
    }

    float4 bv = make_float4(0.f, 0.f, 0.f, 0.f);
    if (bias) bv = *(const float4*)&bias[c0 + (tx << 2)];
#pragma unroll
    for (int r = 0; r < 4; ++r) {
        int n = n0 + ty * 4 + r;
        if (n < nrows) {
            float4 v = make_float4(acc[r][0] + bv.x, acc[r][1] + bv.y,
                                   acc[r][2] + bv.z, acc[r][3] + bv.w);
            size_t o = (size_t)n * ldc + c0 + (tx << 2);
            *(float4*)&C[o] = v;
            if (C2) *(float4*)&C2[o] = v;
        }
    }
}

// ---------------- fused aggregate (CSR) + edge-type GEMM ------------------------
// a[n] = sum_t (sum_{e->n,t} h[src]) @ W_t + sum_t cnt_t(n)*b_t
// edge_W (input layout [t][h][k]) IS the stacked [256][64] weight matrix.
#define SAG 260
__global__ __launch_bounds__(256) void agg_a(
    const float* __restrict__ edge_W, const float* __restrict__ edge_b)
{
    extern __shared__ float sm[];
    float* sA  = sm;                   // [64 nodes][SAG]  (256 K + pad)
    float* sW  = sm + 64 * SAG;        // [64][SP]
    float* sEB = sW + 64 * SP;         // [4][64]
    const int tid = threadIdx.x;
    const int lane = tid & 31, w = tid >> 5;
    const int nblk = blockIdx.x * 64;

    if (tid < 256) sEB[tid] = edge_b[tid];

    // aggregation: warp per node (8 nodes per warp)
    for (int i = 0; i < 8; ++i) {
        int nloc = w * 8 + i;
        int n = nblk + nloc;
        float2 a0 = {0.f, 0.f}, a1 = {0.f, 0.f}, a2 = {0.f, 0.f}, a3 = {0.f, 0.f};
        if (n < NN) {
            int e = g_rowstart[n], ee = g_rowstart[n + 1];
#pragma unroll 2
            for (; e < ee; ++e) {
                int val = g_eidx[e];
                int s = val >> 2, t = val & 3;
                float2 v = *(const float2*)&g_h[(size_t)s * 64 + lane * 2];
                if (t == 0)      { a0.x += v.x; a0.y += v.y; }
                else if (t == 1) { a1.x += v.x; a1.y += v.y; }
                else if (t == 2) { a2.x += v.x; a2.y += v.y; }
                else             { a3.x += v.x; a3.y += v.y; }
            }
        }
        float* row = &sA[nloc * SAG + lane * 2];
        *(float2*)&row[0]   = a0;
        *(float2*)&row[64]  = a1;
        *(float2*)&row[128] = a2;
        *(float2*)&row[192] = a3;
    }
    __syncthreads();

    // GEMM: [64 x 256] (shared) @ [256 x 64] (edge_W)
    const int tx = tid & 15, ty = tid >> 4;
    float acc[4][4] = {};
    for (int kc = 0; kc < 4; ++kc) {
#pragma unroll
        for (int i = 0; i < 4; ++i) {
            int idx = tid + i * 256;
            int k = idx >> 4, cq = (idx & 15) << 2;
            *(float4*)&sW[k * SP + cq] = *(const float4*)&edge_W[(size_t)(kc * 64 + k) * 64 + cq];
        }
        __syncthreads();
        const int kg = kc * 64;
#pragma unroll
        for (int kk = 0; kk < 64; ++kk) {
            float4 wv = *(const float4*)&sW[kk * SP + (tx << 2)];
            float a0 = sA[(ty * 4 + 0) * SAG + kg + kk];
            float a1 = sA[(ty * 4 + 1) * SAG + kg + kk];
            float a2 = sA[(ty * 4 + 2) * SAG + kg + kk];
            float a3 = sA[(ty * 4 + 3) * SAG + kg + kk];
            acc[0][0] += a0 * wv.x; acc[0][1] += a0 * wv.y; acc[0][2] += a0 * wv.z; acc[0][3] += a0 * wv.w;
            acc[1][0] += a1 * wv.x; acc[1][1] += a1 * wv.y; acc[1][2] += a1 * wv.z; acc[1][3] += a1 * wv.w;
            acc[2][0] += a2 * wv.x; acc[2][1] += a2 * wv.y; acc[2][2] += a2 * wv.z; acc[2][3] += a2 * wv.w;
            acc[3][0] += a3 * wv.x; acc[3][1] += a3 * wv.y; acc[3][2] += a3 * wv.z; acc[3][3] += a3 * wv.w;
        }
        __syncthreads();
    }

#pragma unroll
    for (int r = 0; r < 4; ++r) {
        int n = nblk + ty * 4 + r;
        if (n < NN) {
            int4 cnt = *(const int4*)&g_cnt4[n * 4];
            int c = tx << 2;
            float4 v;
            v.x = acc[r][0] + cnt.x * sEB[c + 0] + cnt.y * sEB[64 + c + 0] + cnt.z * sEB[128 + c + 0] + cnt.w * sEB[192 + c + 0];
            v.y = acc[r][1] + cnt.x * sEB[c + 1] + cnt.y * sEB[64 + c + 1] + cnt.z * sEB[128 + c + 1] + cnt.w * sEB[192 + c + 1];
            v.z = acc[r][2] + cnt.x * sEB[c + 2] + cnt.y * sEB[64 + c + 2] + cnt.z * sEB[128 + c + 2] + cnt.w * sEB[192 + c + 2];
            v.w = acc[r][3] + cnt.x * sEB[c + 3] + cnt.y * sEB[64 + c + 3] + cnt.z * sEB[128 + c + 3] + cnt.w * sEB[192 + c + 3];
            *(float4*)&g_a[(size_t)n * 64 + c] = v;
        }
    }
}

// ---------------- GRU elementwise (vectorized) ----------------------------------
__global__ void gru4()
{
    int i = blockIdx.x * blockDim.x + threadIdx.x;   // over NN*16
    if (i >= NN * 16) return;
    int n = i >> 4, q = (i & 15) << 2;
    float4 rv = *(const float4*)&g_rz[(size_t)n * 128 + q];
    float4 zv = *(const float4*)&g_rz[(size_t)n * 128 + 64 + q];
    float4 iv = *(const float4*)&g_in[(size_t)i * 4];
    float4 hv = *(const float4*)&g_hn[(size_t)i * 4];
    float4 h  = *(const float4*)&g_h[(size_t)i * 4];
#define GRU1(comp)                                                     \
    {                                                                  \
        float r = 1.f / (1.f + expf(-rv.comp));                        \
        float z = 1.f / (1.f + expf(-zv.comp));                        \
        float nv = tanhf(iv.comp + r * hv.comp);                       \
        h.comp = (1.f - z) * nv + z * h.comp;                          \
    }
    GRU1(x) GRU1(y) GRU1(z) GRU1(w)
#undef GRU1
    *(float4*)&g_h[(size_t)i * 4] = h;
}

// ---------------- attention pooling ---------------------------------------------
__device__ void atomicMaxFloat(float* addr, float v)
{
    int* ia = (int*)addr;
    int old = *ia;
    while (true) {
        float f = __int_as_float(old);
        if (f >= v) break;
        int assumed = old;
        old = atomicCAS(ia, assumed, __float_as_int(v));
        if (old == assumed) break;
    }
}

__global__ void init_pool()
{
    int tid = threadIdx.x;
    if (tid < BB) {
        g_gmax[tid] = __int_as_float(0xff800000);
        g_den[tid] = 0.f;
    }
    for (int i = tid; i < BB * 128; i += 256) g_rsum[i] = 0.f;
}

__global__ __launch_bounds__(256) void gate_kernel(
    const int* __restrict__ gid, const float* __restrict__ gW,
    const float* __restrict__ gb)
{
    int gtid = blockIdx.x * blockDim.x + threadIdx.x;
    int n = gtid >> 5;
    if (n >= NN) return;
    int lane = gtid & 31;
    int j0 = lane << 2;
    float4 fv = (j0 < 64) ? *(const float4*)&g_h[(size_t)n * 64 + j0]
                          : *(const float4*)&g_h0[(size_t)n * 64 + j0 - 64];
    float4 wv = *(const float4*)&gW[j0];
    float s = fv.x * wv.x + fv.y * wv.y + fv.z * wv.z + fv.w * wv.w;
#pragma unroll
    for (int o = 16; o; o >>= 1) s += __shfl_xor_sync(0xffffffffu, s, o);
    if (lane == 0) {
        float g = s + gb[0];
        g_gate[n] = g;
        atomicMaxFloat(&g_gmax[gid[n]], g);
    }
}

__global__ __launch_bounds__(256) void pool_kernel(const int* __restrict__ gid)
{
    int gtid = blockIdx.x * blockDim.x + threadIdx.x;
    int n = gtid >> 5;
    if (n >= NN) return;
    int lane = gtid & 31;
    int g = gid[n];
    float gm = g_gmax[g];
    if (!isfinite(gm)) gm = 0.f;
    float e = expf(g_gate[n] - gm);
    int j0 = lane << 2;
    float4 fv = (j0 < 64) ? *(const float4*)&g_h[(size_t)n * 64 + j0]
                          : *(const float4*)&g_h0[(size_t)n * 64 + j0 - 64];
    float* rp = &g_rsum[g * 128 + j0];
    atomicAdd(rp + 0, e * fv.x);
    atomicAdd(rp + 1, e * fv.y);
    atomicAdd(rp + 2, e * fv.z);
    atomicAdd(rp + 3, e * fv.w);
    if (lane == 0) atomicAdd(&g_den[g], e);
}

__global__ void out_kernel(const float* __restrict__ oW,
                           const float* __restrict__ ob,
                           float* __restrict__ out)
{
    int b = blockIdx.x, tid = threadIdx.x;   // 128 threads
    float dn = g_den[b];
    float inv = (dn > 0.f) ? (1.f / dn) : 0.f;
    float r = g_rsum[b * 128 + tid] * inv;
    float p0 = r * oW[tid * 2 + 0];
    float p1 = r * oW[tid * 2 + 1];
#pragma unroll
    for (int o = 16; o; o >>= 1) {
        p0 += __shfl_xor_sync(0xffffffffu, p0, o);
        p1 += __shfl_xor_sync(0xffffffffu, p1, o);
    }
    __shared__ float s0[4], s1[4];
    if ((tid & 31) == 0) { s0[tid >> 5] = p0; s1[tid >> 5] = p1; }
    __syncthreads();
    if (tid == 0) {
        out[b * 2 + 0] = s0[0] + s0[1] + s0[2] + s0[3] + ob[0];
        out[b * 2 + 1] = s1[0] + s1[1] + s1[2] + s1[3] + ob[1];
    }
}

// ---------------- host orchestration --------------------------------------------
extern "C" void kernel_launch(void* const* d_in, const int* in_sizes, int n_in,
                              void* d_out, int out_size)
{
    const float* ann      = (const float*)d_in[0];
    const int*   src      = (const int*)d_in[1];
    const int*   dst      = (const int*)d_in[2];
    const int*   ety      = (const int*)d_in[3];
    const int*   gid      = (const int*)d_in[4];
    const float* reduce_W = (const float*)d_in[5];
    const float* reduce_b = (const float*)d_in[6];
    const float* edge_W   = (const float*)d_in[7];
    const float* edge_b   = (const float*)d_in[8];
    const float* gru_Wi   = (const float*)d_in[9];
    const float* gru_bi   = (const float*)d_in[10];
    const float* gru_Wh   = (const float*)d_in[11];
    const float* gru_bh   = (const float*)d_in[12];
    const float* gate_W   = (const float*)d_in[13];
    const float* gate_b   = (const float*)d_in[14];
    const float* out_W    = (const float*)d_in[15];
    const float* out_b    = (const float*)d_in[16];
    float* out = (float*)d_out;

    float *ph, *ph0, *pa, *prz, *pin, *phn, *pWrz, *pWin, *pWhn, *pbrz, *pbin, *pbhn;
    cudaGetSymbolAddress((void**)&ph,   g_h);
    cudaGetSymbolAddress((void**)&ph0,  g_h0);
    cudaGetSymbolAddress((void**)&pa,   g_a);
    cudaGetSymbolAddress((void**)&prz,  g_rz);
    cudaGetSymbolAddress((void**)&pin,  g_in);
    cudaGetSymbolAddress((void**)&phn,  g_hn);
    cudaGetSymbolAddress((void**)&pWrz, g_Wrz);
    cudaGetSymbolAddress((void**)&pWin, g_Win);
    cudaGetSymbolAddress((void**)&pWhn, g_Whn);
    cudaGetSymbolAddress((void**)&pbrz, g_brz);
    cudaGetSymbolAddress((void**)&pbin, g_bin);
    cudaGetSymbolAddress((void**)&pbhn, g_bhn);

    const int GB = (NN + 63) / 64;                 // 1563
    const int GEMM_SMEM = 2 * 64 * SP * 4;         // 34816 B
    const int AGG_SMEM  = (64 * SAG + 64 * SP + 256) * 4;  // 84992 B
    cudaFuncSetAttribute(agg_a, cudaFuncAttributeMaxDynamicSharedMemorySize, AGG_SMEM);

    // CSR build (per launch; graph inputs are launch-constant data)
    zero_cnt<<<(NN * 4 + 255) / 256, 256>>>();
    hist_kernel<<<(EE + 255) / 256, 256>>>(dst, ety);
    scan_kernel<<<1, 1024>>>();
    fill_kernel<<<(EE + 255) / 256, 256>>>(src, dst, ety);
    pack2<<<(24832 + 255) / 256, 256>>>(gru_Wi, gru_Wh, gru_bi, gru_bh);

    // h0 = annotation @ reduce_W + reduce_b  (also into h)
    gemm_t<<<dim3(GB, 1), 256, GEMM_SMEM>>>(ann, nullptr, AA, 4, reduce_W, HH,
                                            reduce_b, ph0, ph, HH, NN);
    init_pool<<<1, 256>>>();

    for (int s = 0; s < NSTEPS; ++s) {
        agg_a<<<GB, 256, AGG_SMEM>>>(edge_W, edge_b);
        // rz = [a|h] @ Wrz + (bi+bh)[0:128]
        gemm_t<<<dim3(GB, 2), 256, GEMM_SMEM>>>(pa, ph, HH, 2, pWrz, 128,
                                                pbrz, prz, nullptr, 128, NN);
        // i_n = a @ Win + bi_n ; h_n = h @ Whn + bh_n
        gemm_t<<<dim3(GB, 1), 256, GEMM_SMEM>>>(pa, nullptr, HH, 1, pWin, HH,
                                                pbin, pin, nullptr, HH, NN);
        gemm_t<<<dim3(GB, 1), 256, GEMM_SMEM>>>(ph, nullptr, HH, 1, pWhn, HH,
                                                pbhn, phn, nullptr, HH, NN);
        gru4<<<(NN * 16 + 255) / 256, 256>>>();
    }

    gate_kernel<<<(NN * 32 + 255) / 256, 256>>>(gid, gate_W, gate_b);
    pool_kernel<<<(NN * 32 + 255) / 256, 256>>>(gid);
    out_kernel<<<BB, 128>>>(out_W, out_b, out);
}